// round 1
// baseline (speedup 1.0000x reference)
#include <cuda_runtime.h>
#include <math.h>
#include <stdint.h>

// Problem dims (fixed by the dataset)
#define NCUT 200000
#define GOI  500
#define BB   512
#define LL   16
#define CC   224
#define GTOT 20000
#define LOG2PI 1.8378770664093453

// ---------------- device scratch (static; no allocations allowed) ------------
__device__ float  g_lw[GOI * LL * CC];   // gathered logit weights [g][l][c]  (7.2MB)
__device__ float4 g_spl[GOI * CC];       // per-gene spline params {uh, ww, loc, w} (1.8MB)
__device__ float  g_z[BB * GTOT];        // unnormalized log-rho (41MB)
__device__ float  g_logZ[BB];
__device__ int    g_off[GOI + 1];        // histogram -> offsets
__device__ int    g_woff[GOI];           // scatter cursors
__device__ int    g_sorted[NCUT];        // cut ids sorted by g2
__device__ double g_acc[2];              // [0] = lik sum, [1] = prior sum

// ---------------- K0: init accumulators + histogram ----------------
__global__ void k_init() {
    int t = threadIdx.x;
    if (t < 2) g_acc[t] = 0.0;
    for (int i = t; i <= GOI; i += blockDim.x) g_off[i] = 0;
}

// ---------------- K1: per-gene precompute (softmax widths, cumsum, gather) ---
__global__ void k_pergene(const int* __restrict__ genes_oi,
                          const float* __restrict__ logit_weight,
                          const float* __restrict__ rho_weight,
                          const float* __restrict__ uh,
                          const float* __restrict__ uw) {
    int g = blockIdx.x, t = threadIdx.x;
    int gene = genes_oi[g];

    float psum = 0.f;
    const float* lwr = logit_weight + (size_t)gene * (LL * CC);
    for (int i = t; i < LL * CC; i += blockDim.x) {
        float v = lwr[i];
        g_lw[g * (LL * CC) + i] = v;
        psum -= 0.5f * v * v;
    }
    if (t < LL) { float v = rho_weight[gene * LL + t]; psum -= 0.5f * v * v; }

    __shared__ float s_red[128];
    __shared__ float s_w[128];
    __shared__ float s_scan[128];

    const int nh_t[3] = {128, 64, 32};
    const int oh_t[3] = {0, 128, 192};
    const int ow_t[3] = {0, 127, 190};
    const float* uhr = uh + (size_t)gene * CC;
    const float* uwr = uw + (size_t)gene * 221;

    for (int s = 0; s < 3; s++) {
        int nh = nh_t[s], nw = nh - 1, oh = oh_t[s], ow = ow_t[s];
        float uwv = (t < nw) ? uwr[ow + t] : -1e30f;
        // softmax over nw width logits
        s_red[t] = uwv; __syncthreads();
        for (int o = 64; o; o >>= 1) { if (t < o) s_red[t] = fmaxf(s_red[t], s_red[t + o]); __syncthreads(); }
        float mx = s_red[0]; __syncthreads();
        float e = (t < nw) ? __expf(uwv - mx) : 0.f;
        s_red[t] = e; __syncthreads();
        for (int o = 64; o; o >>= 1) { if (t < o) s_red[t] += s_red[t + o]; __syncthreads(); }
        float inv = 1.0f / s_red[0]; __syncthreads();
        float w = e * inv;
        s_w[t] = w;
        s_scan[t] = w;
        __syncthreads();
        // inclusive Hillis-Steele scan
        for (int o = 1; o < 128; o <<= 1) {
            float v = (t >= o) ? s_scan[t - o] : 0.f;
            __syncthreads();
            s_scan[t] += v;
            __syncthreads();
        }
        if (t < nh) {
            float loc = (t == 0) ? 0.f : ((t == nw) ? 1.0f : s_scan[t - 1]);
            float wl = (t >= 1) ? s_w[t - 1] : 0.f;
            float wr = (t <= nw - 1) ? w : 0.f;
            float wwv = 0.5f * (wl + wr);
            float wst = (t < nw) ? w : 0.f;
            g_spl[g * CC + oh + t] = make_float4(uhr[oh + t], wwv, loc, wst);
        }
        __syncthreads();
    }

    s_red[t] = psum; __syncthreads();
    for (int o = 64; o; o >>= 1) { if (t < o) s_red[t] += s_red[t + o]; __syncthreads(); }
    if (t == 0) atomicAdd(&g_acc[1], (double)s_red[0]);
}

// ---------------- counting sort of cuts by g2 = ci % G ----------------
__global__ void k_hist(const int* __restrict__ lci, int n, int G) {
    int i = blockIdx.x * blockDim.x + threadIdx.x;
    if (i < n) atomicAdd(&g_off[lci[i] % G], 1);
}

__global__ void k_scan(int G) {
    __shared__ int sc[512];
    int t = threadIdx.x;
    int v = (t < G) ? g_off[t] : 0;
    sc[t] = v; __syncthreads();
    for (int o = 1; o < 512; o <<= 1) {
        int x = (t >= o) ? sc[t - o] : 0;
        __syncthreads();
        sc[t] += x;
        __syncthreads();
    }
    int excl = sc[t] - v;
    if (t <= G) g_off[t] = excl;
    if (t < G)  g_woff[t] = excl;
}

__global__ void k_scatter(const int* __restrict__ lci, int n, int G) {
    int i = blockIdx.x * blockDim.x + threadIdx.x;
    if (i < n) {
        int g = lci[i] % G;
        int p = atomicAdd(&g_woff[g], 1);
        g_sorted[p] = i;
    }
}

// ---------------- K2a: z = log(rho_bias) + clustering @ rho_weight^T --------
__global__ void k_z(const float* __restrict__ clustering,
                    const float* __restrict__ rho_weight,
                    const float* __restrict__ rho_bias, int GT) {
    int j = blockIdx.x * blockDim.x + threadIdx.x;
    if (j >= GT) return;
    int b0 = blockIdx.y * 8;
    float lb = __logf(rho_bias[j]);
    const float4* rw = (const float4*)(rho_weight + (size_t)j * LL);
    float4 r0 = rw[0], r1 = rw[1], r2 = rw[2], r3 = rw[3];
#pragma unroll
    for (int bi = 0; bi < 8; bi++) {
        int b = b0 + bi;
        const float4* cp = (const float4*)(clustering + (size_t)b * LL);
        float4 c0 = cp[0], c1 = cp[1], c2 = cp[2], c3 = cp[3];
        float z = lb;
        z = fmaf(c0.x, r0.x, z); z = fmaf(c0.y, r0.y, z); z = fmaf(c0.z, r0.z, z); z = fmaf(c0.w, r0.w, z);
        z = fmaf(c1.x, r1.x, z); z = fmaf(c1.y, r1.y, z); z = fmaf(c1.z, r1.z, z); z = fmaf(c1.w, r1.w, z);
        z = fmaf(c2.x, r2.x, z); z = fmaf(c2.y, r2.y, z); z = fmaf(c2.z, r2.z, z); z = fmaf(c2.w, r2.w, z);
        z = fmaf(c3.x, r3.x, z); z = fmaf(c3.y, r3.y, z); z = fmaf(c3.z, r3.z, z); z = fmaf(c3.w, r3.w, z);
        g_z[(size_t)b * GT + j] = z;
    }
}

// ---------------- K2b: per-row online logsumexp ----------------
__global__ void k_lse(int GT) {
    int b = blockIdx.x, t = threadIdx.x;
    const float* zr = g_z + (size_t)b * GT;
    float m = -1e30f, s = 0.f;
    for (int j = t; j < GT; j += blockDim.x) {
        float v = zr[j];
        if (v > m) { s = s * __expf(m - v) + 1.f; m = v; }
        else       { s += __expf(v - m); }
    }
    __shared__ float sm[256], ss[256];
    sm[t] = m; ss[t] = s; __syncthreads();
    for (int o = 128; o; o >>= 1) {
        if (t < o) {
            float m1 = sm[t], s1 = ss[t], m2 = sm[t + o], s2 = ss[t + o];
            float M = fmaxf(m1, m2);
            sm[t] = M;
            ss[t] = s1 * __expf(m1 - M) + s2 * __expf(m2 - M);
        }
        __syncthreads();
    }
    if (t == 0) g_logZ[b] = sm[0] + logf(ss[0]);
}

// ---------------- K3: main per-cut spline kernel ----------------
template <int K>
__device__ __forceinline__ float selK(const float (&h)[K], int j) {
    if constexpr (K == 1) return h[0];
    else if constexpr (K == 2) return j ? h[1] : h[0];
    else return (j < 2) ? (j == 0 ? h[0] : h[1]) : (j == 2 ? h[2] : h[3]);
}

template <int NH, int OH, int K>
__device__ __forceinline__ void spline_step(const float* __restrict__ s_lw,
                                            const float4* __restrict__ splg,
                                            const float (&cl)[16],
                                            int lane, float& x, float& lad) {
    float uhv[K], wwv[K], locv[K], wv[K];
#pragma unroll
    for (int j = 0; j < K; j++) {
        float4 sp = __ldg(splg + OH + lane * K + j);
        uhv[j] = sp.x; wwv[j] = sp.y; locv[j] = sp.z; wv[j] = sp.w;
    }
    float d[K];
#pragma unroll
    for (int j = 0; j < K; j++) d[j] = 0.f;
#pragma unroll
    for (int l = 0; l < 16; l++) {
        const float* base = s_lw + l * CC + OH + lane * K;
        if constexpr (K == 4) {
            float4 v = *(const float4*)base;
            d[0] = fmaf(cl[l], v.x, d[0]);
            d[1] = fmaf(cl[l], v.y, d[1]);
            d[2] = fmaf(cl[l], v.z, d[2]);
            d[3] = fmaf(cl[l], v.w, d[3]);
        } else if constexpr (K == 2) {
            float2 v = *(const float2*)base;
            d[0] = fmaf(cl[l], v.x, d[0]);
            d[1] = fmaf(cl[l], v.y, d[1]);
        } else {
            d[0] = fmaf(cl[l], *base, d[0]);
        }
    }
    float h[K];
#pragma unroll
    for (int j = 0; j < K; j++) h[j] = __expf(uhv[j] + d[j]);

    int cnt = 0;
#pragma unroll
    for (int j = 0; j < K; j++) cnt += (x >= locv[j]) ? 1 : 0;
#pragma unroll
    for (int o = 16; o; o >>= 1) cnt += __shfl_xor_sync(0xffffffffu, cnt, o);
    int bin = cnt - 1;
    bin = bin < 0 ? 0 : bin;
    bin = bin > NH - 2 ? NH - 2 : bin;

    float wprev = __shfl_up_sync(0xffffffffu, wv[K - 1], 1);
    float area = 0.f, cdf = 0.f;
    float wim1 = wprev;
#pragma unroll
    for (int j = 0; j < K; j++) {
        int i = lane * K + j;
        area = fmaf(h[j], wwv[j], area);
        float ct = 0.f;
        if (i < bin) ct += 0.5f * wv[j];
        if (i >= 1 && i <= bin) ct += 0.5f * wim1;
        cdf = fmaf(h[j], ct, cdf);
        wim1 = wv[j];
    }
#pragma unroll
    for (int o = 16; o; o >>= 1) {
        area += __shfl_xor_sync(0xffffffffu, area, o);
        cdf  += __shfl_xor_sync(0xffffffffu, cdf, o);
    }

    int jb  = bin & (K - 1), lb  = bin / K;
    int bp  = bin + 1;
    int jb1 = bp & (K - 1),  lb1 = bp / K;
    float hl_un = __shfl_sync(0xffffffffu, selK<K>(h, jb),  lb);
    float hr_un = __shfl_sync(0xffffffffu, selK<K>(h, jb1), lb1);

    float4 spb = __ldg(splg + OH + bin);   // {uh, ww, loc_l, w_b}
    float inv = __fdividef(1.0f, area);
    float hl = hl_un * inv, hr = hr_un * inv, cdfl = cdf * inv;
    float alpha = __fdividef(x - spb.z, spb.w);
    x = (0.5f * (hr - hl) * alpha + hl) * spb.w * alpha + cdfl;
    lad += __logf(fmaf(hr - hl, alpha, hl));
}

__global__ void __launch_bounds__(256) k_main(const float* __restrict__ coordinates,
                                              const int* __restrict__ local_gene_ix,
                                              const int* __restrict__ local_cellxgene_ix,
                                              const int* __restrict__ localcellxgene_ix,
                                              const float* __restrict__ clustering,
                                              int G, int GT, float logGT) {
    __shared__ __align__(16) float s_lw[LL * CC];
    int g = blockIdx.x;
    int t = threadIdx.x;
    for (int i = t; i < LL * CC; i += 256) s_lw[i] = g_lw[g * (LL * CC) + i];
    __syncthreads();

    int start = g_off[g], end = g_off[g + 1];
    int wid = t >> 5, lane = t & 31;
    double acc = 0.0;

    for (int k = start + wid; k < end; k += 8) {
        int n  = g_sorted[k];
        float x = coordinates[n];
        int gl = local_gene_ix[n];
        int ci = local_cellxgene_ix[n];
        int li = localcellxgene_ix[n];
        int b  = ci / G;

        const float4* cp = (const float4*)(clustering + (size_t)b * LL);
        float4 c0 = cp[0], c1 = cp[1], c2 = cp[2], c3 = cp[3];
        float cl[16] = {c0.x, c0.y, c0.z, c0.w, c1.x, c1.y, c1.z, c1.w,
                        c2.x, c2.y, c2.z, c2.w, c3.x, c3.y, c3.z, c3.w};

        const float4* splg = g_spl + (size_t)gl * CC;
        float lad = 0.f;
        spline_step<128, 0,   4>(s_lw, splg, cl, lane, x, lad);
        spline_step<64,  128, 2>(s_lw, splg, cl, lane, x, lad);
        spline_step<32,  192, 1>(s_lw, splg, cl, lane, x, lad);

        float zc = __ldg(&g_z[li]);
        int row = li / GT;
        float lov = zc - g_logZ[row] + logGT;
        if (lane == 0) acc += (double)(lad + lov);
    }

    __syncthreads();
    __shared__ double s_acc[8];
    if (lane == 0) s_acc[wid] = acc;
    __syncthreads();
    if (t == 0) {
        double tot = 0.0;
        for (int i = 0; i < 8; i++) tot += s_acc[i];
        atomicAdd(&g_acc[0], tot);
    }
}

// ---------------- K4: finalize ----------------
__global__ void k_final(float* out, int G) {
    double cnt = (double)G * (double)(LL * CC + LL);  // prior element count
    out[0] = (float)(-g_acc[0] - g_acc[1] + 0.5 * LOG2PI * cnt);
}

// ---------------- launch ----------------
extern "C" void kernel_launch(void* const* d_in, const int* in_sizes, int n_in,
                              void* d_out, int out_size) {
    const float* clustering   = (const float*)d_in[0];
    const float* coordinates  = (const float*)d_in[1];
    const int*   genes_oi     = (const int*)d_in[2];
    const int*   local_gene_ix= (const int*)d_in[3];
    const int*   lci          = (const int*)d_in[4];   // local_cellxgene_ix
    const int*   lcgi         = (const int*)d_in[5];   // localcellxgene_ix
    const float* logit_weight = (const float*)d_in[6];
    const float* rho_weight   = (const float*)d_in[7];
    const float* rho_bias     = (const float*)d_in[8];
    const float* uh           = (const float*)d_in[9];
    const float* uw           = (const float*)d_in[10];

    int N  = in_sizes[1];
    int G  = in_sizes[2];
    int B  = in_sizes[0] / LL;
    int GT = in_sizes[8];

    k_init<<<1, 512>>>();
    k_pergene<<<G, 128>>>(genes_oi, logit_weight, rho_weight, uh, uw);
    k_hist<<<(N + 255) / 256, 256>>>(lci, N, G);
    k_scan<<<1, 512>>>(G);
    k_scatter<<<(N + 255) / 256, 256>>>(lci, N, G);
    k_z<<<dim3((GT + 255) / 256, B / 8), 256>>>(clustering, rho_weight, rho_bias, GT);
    k_lse<<<B, 256>>>(GT);
    k_main<<<G, 256>>>(coordinates, local_gene_ix, lci, lcgi, clustering,
                       G, GT, logf((float)GT));
    k_final<<<1, 1>>>((float*)d_out, G);
}